// round 7
// baseline (speedup 1.0000x reference)
#include <cuda_runtime.h>

#define DIM   100
#define KBS   4950
#define NN    (DIM * DIM)          // 10000
#define MAXB  2048                 // max supported batch
#define KC    25                   // K-chunk
#define ASTR  (KC + 1)             // 26, padded
#define BSTR  (DIM + 1)            // 101, padded

// Clamp for loads: always lands in-bounds.
#define CLAMP(i, n) ((i) < (n) ? (i) : ((n) - 1))

// Sanctioned scratch (__device__ globals; no runtime allocation).
__device__ float2 g_U[NN];
__device__ float2 g_L[MAXB * NN];

// ---------------------------------------------------------------------------
// Kernel 1: build U = D * T_K ... T_1.  One CTA per column.
// ---------------------------------------------------------------------------
__global__ void build_U(const float* __restrict__ theta,
                        const float* __restrict__ phi,
                        const float* __restrict__ diag,
                        int n_th, int n_ph, int n_dg) {
    __shared__ float2 col[DIM];
    const int c   = CLAMP(blockIdx.x, DIM);
    const int tid = threadIdx.x;

    for (int r = tid; r < DIM; r += blockDim.x)
        col[CLAMP(r, DIM)] = make_float2(r == c ? 1.0f : 0.0f, 0.0f);
    __syncthreads();

    int off = 0;
    for (int layer = 0; layer < DIM; ++layer) {
        const int start = layer & 1;
        const int np    = (DIM - start) >> 1;
        if (tid < np) {
            const int m  = CLAMP(start + 2 * tid, DIM - 1);
            const int gi = off + tid;
            const float th = theta[CLAMP(gi, n_th)];
            const float ph = phi[CLAMP(gi, n_ph)];
            const float cc = cosf(th);
            const float ss = sinf(th);
            float sp, cp;
            sincosf(ph, &sp, &cp);
            const float2 rm = col[m];
            const float2 rn = col[m + 1];
            const float er = cp * rm.x - sp * rm.y;   // e^{i ph} * rm
            const float ei = cp * rm.y + sp * rm.x;
            col[m]     = make_float2(cc * er - ss * rn.x, cc * ei - ss * rn.y);
            col[m + 1] = make_float2(ss * er + cc * rn.x, ss * ei + cc * rn.y);
        }
        off += np;
        __syncthreads();
    }

    for (int r = tid; r < DIM; r += blockDim.x) {
        float sp, cp;
        sincosf(diag[CLAMP(r, n_dg)], &sp, &cp);
        const float2 v = col[CLAMP(r, DIM)];
        const int gi = r * DIM + c;
        if (gi < NN)
            g_U[gi] = make_float2(cp * v.x - sp * v.y,
                                  cp * v.y + sp * v.x);
    }
}

// ---------------------------------------------------------------------------
// Kernel 2: GEMM1  L_b = U @ X_b.  One CTA per batch, 500 active threads,
// 5x4 complex microtiles, K-chunked, static smem 41.0 KB.
// ---------------------------------------------------------------------------
__global__ void __launch_bounds__(512, 1)
gemm1_UX(const float* __restrict__ xre,
         const float* __restrict__ xim,
         int x_elems, int l_elems) {
    __shared__ float2 As[DIM * ASTR];   // U rows   [row][kk]
    __shared__ float2 Bs[KC * BSTR];    // X chunk  [kk][col]

    const int b    = blockIdx.x;
    const int tid  = threadIdx.x;
    const int base = b * NN;

    const bool active = tid < 500;
    const int ti = tid / 25;
    const int tj = tid - ti * 25;
    const int i0 = ti * 5;
    const int j0 = tj * 4;

    float accx[5][4], accy[5][4];
    #pragma unroll
    for (int r = 0; r < 5; ++r)
        #pragma unroll
        for (int c = 0; c < 4; ++c) { accx[r][c] = 0.0f; accy[r][c] = 0.0f; }

    for (int kc = 0; kc < DIM; kc += KC) {
        for (int e = tid; e < DIM * KC; e += blockDim.x) {
            const int row = e / KC;
            const int kk  = e - row * KC;
            As[CLAMP(row * ASTR + kk, DIM * ASTR)] =
                g_U[CLAMP(row * DIM + kc + kk, NN)];
        }
        for (int e = tid; e < KC * DIM; e += blockDim.x) {
            const int kk  = e / DIM;
            const int col = e - kk * DIM;
            const int gidx = CLAMP(base + (kc + kk) * DIM + col, x_elems);
            Bs[CLAMP(kk * BSTR + col, KC * BSTR)] =
                make_float2(xre[gidx], xim[gidx]);
        }
        __syncthreads();

        if (active) {
            #pragma unroll
            for (int kk = 0; kk < KC; ++kk) {
                float2 a[5], bb[4];
                #pragma unroll
                for (int r = 0; r < 5; ++r)
                    a[r] = As[CLAMP((i0 + r) * ASTR + kk, DIM * ASTR)];
                #pragma unroll
                for (int c = 0; c < 4; ++c)
                    bb[c] = Bs[CLAMP(kk * BSTR + j0 + c, KC * BSTR)];
                #pragma unroll
                for (int r = 0; r < 5; ++r)
                    #pragma unroll
                    for (int c = 0; c < 4; ++c) {
                        accx[r][c] = fmaf(a[r].x, bb[c].x,
                                     fmaf(-a[r].y, bb[c].y, accx[r][c]));
                        accy[r][c] = fmaf(a[r].x, bb[c].y,
                                     fmaf( a[r].y, bb[c].x, accy[r][c]));
                    }
            }
        }
        __syncthreads();
    }

    if (active) {
        #pragma unroll
        for (int r = 0; r < 5; ++r)
            #pragma unroll
            for (int c = 0; c < 4; ++c) {
                const int idx = base + (i0 + r) * DIM + (j0 + c);
                if (idx < l_elems)
                    g_L[idx] = make_float2(accx[r][c], accy[r][c]);
            }
    }
}

// ---------------------------------------------------------------------------
// Kernel 3: GEMM2  O_b = L_b @ U^H.  Static smem 41.6 KB.
// Output stage is mode-driven:
//   mode 0: store Re(O) only as float  (output dtype float32, out_size=B*N*N)
//   mode 1: store interleaved complex as float2 (buffer holds 2*B*N*N floats)
// All stores bounded by out_floats (capacity in FLOAT units).
// ---------------------------------------------------------------------------
__global__ void __launch_bounds__(512, 1)
gemm2_LUh(float* __restrict__ outf, int out_floats, int mode, int l_elems) {
    __shared__ float2 As[DIM * ASTR];   // L rows  [i][kk]
    __shared__ float2 Us[DIM * ASTR];   // U rows  [j][kk]

    const int b    = blockIdx.x;
    const int tid  = threadIdx.x;
    const int base = b * NN;

    const bool active = tid < 500;
    const int ti = tid / 25;
    const int tj = tid - ti * 25;
    const int i0 = ti * 5;
    const int j0 = tj * 4;

    float ox[5][4], oy[5][4];
    #pragma unroll
    for (int r = 0; r < 5; ++r)
        #pragma unroll
        for (int c = 0; c < 4; ++c) { ox[r][c] = 0.0f; oy[r][c] = 0.0f; }

    for (int kc = 0; kc < DIM; kc += KC) {
        for (int e = tid; e < DIM * KC; e += blockDim.x) {
            const int row = e / KC;
            const int kk  = e - row * KC;
            As[CLAMP(row * ASTR + kk, DIM * ASTR)] =
                g_L[CLAMP(base + row * DIM + kc + kk, l_elems)];
            Us[CLAMP(row * ASTR + kk, DIM * ASTR)] =
                g_U[CLAMP(row * DIM + kc + kk, NN)];
        }
        __syncthreads();

        if (active) {
            #pragma unroll
            for (int kk = 0; kk < KC; ++kk) {
                float2 a[5], u[4];
                #pragma unroll
                for (int r = 0; r < 5; ++r)
                    a[r] = As[CLAMP((i0 + r) * ASTR + kk, DIM * ASTR)];
                #pragma unroll
                for (int c = 0; c < 4; ++c)
                    u[c] = Us[CLAMP((j0 + c) * ASTR + kk, DIM * ASTR)];
                #pragma unroll
                for (int r = 0; r < 5; ++r)
                    #pragma unroll
                    for (int c = 0; c < 4; ++c) {
                        // a * conj(u)
                        ox[r][c] = fmaf(a[r].x, u[c].x,
                                   fmaf( a[r].y, u[c].y, ox[r][c]));
                        oy[r][c] = fmaf(a[r].y, u[c].x,
                                   fmaf(-a[r].x, u[c].y, oy[r][c]));
                    }
            }
        }
        __syncthreads();
    }

    if (active) {
        #pragma unroll
        for (int r = 0; r < 5; ++r)
            #pragma unroll
            for (int c = 0; c < 4; ++c) {
                const int idx = base + (i0 + r) * DIM + (j0 + c);
                if (mode == 0) {
                    if (idx < out_floats)
                        outf[idx] = ox[r][c];                 // real part only
                } else {
                    if (2 * idx + 1 < out_floats)
                        reinterpret_cast<float2*>(outf)[idx] =
                            make_float2(ox[r][c], oy[r][c]);  // interleaved
                }
            }
    }
}

// Diagnostic fallback: binding anomaly -> numeric mismatch, never a crash.
__global__ void diag_mark_kernel(float* out) { out[0] = 0.0f; }

extern "C" void kernel_launch(void* const* d_in, const int* in_sizes, int n_in,
                              void* d_out, int out_size) {
    // Unit detection (elements vs bytes) via the 100-element diag array.
    int smin = 0x7fffffff;
    for (int i = 0; i < n_in; ++i)
        if (in_sizes[i] < smin) smin = in_sizes[i];

    int unit = 0;
    if (smin == DIM)          unit = 1;
    else if (smin == DIM * 4) unit = 4;

    const float* xre = nullptr; const float* xim = nullptr;
    const float* theta = nullptr; const float* phi = nullptr;
    const float* diag = nullptr;
    int nbatch = 0, big = 0;
    bool ok = (unit != 0) && (n_in == 5);

    if (ok) {
        int norm[8];
        int diag_slot = -1;
        for (int i = 0; i < n_in; ++i) {
            norm[i] = in_sizes[i] / unit;
            if (norm[i] == DIM) diag_slot = i;
            if (norm[i] > big) big = norm[i];
        }
        if (diag_slot == 0 && norm[1] == KBS && norm[2] == KBS) {
            // alphabetical metadata order: diag, phi, theta, x_re, x_im
            diag  = (const float*)d_in[0];
            phi   = (const float*)d_in[1];
            theta = (const float*)d_in[2];
            xre   = (const float*)d_in[3];
            xim   = (const float*)d_in[4];
        } else {
            for (int i = 0; i < n_in; ++i) {
                const float* p = (const float*)d_in[i];
                if (norm[i] == KBS)      { if (!theta) theta = p; else phi = p; }
                else if (norm[i] == DIM) { diag = p; }
                else if (norm[i] == big) { if (!xre) xre = p; else xim = p; }
            }
        }
        nbatch = big / NN;
        ok = xre && xim && theta && phi && diag &&
             nbatch > 0 && nbatch <= MAXB && (big == nbatch * NN);
    }

    if (!ok) {
        diag_mark_kernel<<<1, 1>>>((float*)d_out);
        return;
    }

    // ---- Output contract resolution (H*: complex64 was cast to float32) ----
    // mode 0 (real-only float stores)   : out_size == B*N*N      -> cap = want floats
    // mode 1 (interleaved float2 stores): out_size == 2*B*N*N    -> cap = 2*want floats
    //                                     out_size == 8*B*N*N(B) -> cap = 2*want floats
    // else: conservative real-only with cap = min(want, out_size) floats.
    const int want = nbatch * NN;
    int mode, out_floats;
    if      (out_size == want)     { mode = 0; out_floats = want; }
    else if (out_size == 2 * want) { mode = 1; out_floats = 2 * want; }
    else if (out_size == 8 * want) { mode = 1; out_floats = 2 * want; }
    else { mode = 0; out_floats = (out_size < want) ? out_size : want; }

    const int l_elems = nbatch * NN;   // extent of g_L actually used

    build_U<<<DIM, 64>>>(theta, phi, diag, KBS, KBS, DIM);
    gemm1_UX<<<nbatch, 512>>>(xre, xim, big, l_elems);
    gemm2_LUh<<<nbatch, 512>>>((float*)d_out, out_floats, mode, l_elems);
}

// round 8
// speedup vs baseline: 1.4499x; 1.4499x over previous
#include <cuda_runtime.h>
#include <string.h>

#define DIM   100
#define KBS   4950
#define NN    (DIM * DIM)          // 10000
#define MAXB  2048
#define KC    25                   // K-chunk
#define ASTR  (KC + 1)             // 26, padded
#define BSTR  (DIM + 1)            // 101, padded

// Sanctioned scratch (__device__ globals; no runtime allocation).
__device__ float2 g_U[NN];
__device__ float2 g_L[MAXB * NN];
__device__ float4 g_rot[KBS];      // {cos th, sin th, cos ph, sin ph}
__device__ float2 g_dph[DIM];      // {cos d, sin d}

// ---------------- packed f32x2 helpers (Blackwell f32x2 pipe) ----------------
__device__ __forceinline__ unsigned long long pk2(float lo, float hi) {
    unsigned long long r;
    asm("mov.b64 %0, {%1, %2};" : "=l"(r) : "f"(lo), "f"(hi));
    return r;
}
__device__ __forceinline__ unsigned long long f2ull(float2 v) {
    unsigned long long r; memcpy(&r, &v, 8); return r;
}
__device__ __forceinline__ float2 ull2f(unsigned long long v) {
    float2 f; memcpy(&f, &v, 8); return f;
}
__device__ __forceinline__ void fma2(unsigned long long& d,
                                     unsigned long long a,
                                     unsigned long long b) {
    asm("fma.rn.f32x2 %0, %1, %2, %0;" : "+l"(d) : "l"(a), "l"(b));
}

// ---------------------------------------------------------------------------
// Kernel 0: precompute all rotation coefficients ONCE (round-5 build_U made
// 100 CTAs each redundantly evaluate 4950 sincos pairs).
// ---------------------------------------------------------------------------
__global__ void rot_prep(const float* __restrict__ theta,
                         const float* __restrict__ phi,
                         const float* __restrict__ diag) {
    const int i = blockIdx.x * blockDim.x + threadIdx.x;
    if (i < KBS) {
        float st, ct, sp, cp;
        sincosf(theta[i], &st, &ct);
        sincosf(phi[i],   &sp, &cp);
        g_rot[i] = make_float4(ct, st, cp, sp);
    }
    if (i < DIM) {
        float sd, cd;
        sincosf(diag[i], &sd, &cd);
        g_dph[i] = make_float2(cd, sd);
    }
}

// ---------------------------------------------------------------------------
// Kernel 1: build U = D * T_K ... T_1.  One CTA per column; serial layer scan
// with per-layer barrier; coefficients read from g_rot (L2-resident).
// ---------------------------------------------------------------------------
__global__ void build_U() {
    __shared__ float2 col[DIM];
    const int c   = blockIdx.x;
    const int tid = threadIdx.x;          // blockDim = 64

    for (int r = tid; r < DIM; r += 64)
        col[r] = make_float2(r == c ? 1.0f : 0.0f, 0.0f);
    __syncthreads();

    int off = 0;
    for (int layer = 0; layer < DIM; ++layer) {
        const int start = layer & 1;
        const int np    = (DIM - start) >> 1;
        if (tid < np) {
            const float4 rc = g_rot[off + tid];   // {ct, st, cp, sp}
            const int m = start + 2 * tid;
            const float2 rm = col[m];
            const float2 rn = col[m + 1];
            const float er = rc.z * rm.x - rc.w * rm.y;   // e^{i ph} * rm
            const float ei = rc.z * rm.y + rc.w * rm.x;
            col[m]     = make_float2(rc.x * er - rc.y * rn.x,
                                     rc.x * ei - rc.y * rn.y);
            col[m + 1] = make_float2(rc.y * er + rc.x * rn.x,
                                     rc.y * ei + rc.x * rn.y);
        }
        off += np;
        __syncthreads();
    }

    for (int r = tid; r < DIM; r += 64) {
        const float2 d = g_dph[r];
        const float2 v = col[r];
        g_U[r * DIM + c] = make_float2(d.x * v.x - d.y * v.y,
                                       d.x * v.y + d.y * v.x);
    }
}

// ---------------------------------------------------------------------------
// Kernel 2: GEMM1  L_b = U @ X_b  (full complex).
// One CTA per batch, 500 active threads, 5x4 complex microtiles.
// Packed accumulation: acc = (Re, Im);
//   acc += (a.x, a.x) * (b.x, b.y)       [a.x*b.x, a.x*b.y]
//   acc += (-a.y, a.y) * (b.y, b.x)      [-a.y*b.y, a.y*b.x]
// Static smem 41.0 KB. No clamps (bounds proven in launcher).
// ---------------------------------------------------------------------------
__global__ void __launch_bounds__(512)
gemm1_UX(const float* __restrict__ xre, const float* __restrict__ xim) {
    __shared__ float2 As[DIM * ASTR];   // U rows   [row][kk]
    __shared__ float2 Bs[KC * BSTR];    // X chunk  [kk][col]

    const int b    = blockIdx.x;
    const int tid  = threadIdx.x;
    const int base = b * NN;

    const bool active = tid < 500;
    const int ti = tid / 25;
    const int tj = tid - ti * 25;
    const int i0 = ti * 5;
    const int j0 = tj * 4;

    unsigned long long acc[5][4];
    #pragma unroll
    for (int r = 0; r < 5; ++r)
        #pragma unroll
        for (int c = 0; c < 4; ++c) acc[r][c] = 0ull;

    for (int kc = 0; kc < DIM; kc += KC) {
        for (int e = tid; e < DIM * KC; e += 512) {
            const int row = e / KC;
            const int kk  = e - row * KC;
            As[row * ASTR + kk] = g_U[row * DIM + kc + kk];
        }
        for (int e = tid; e < KC * DIM; e += 512) {
            const int kk  = e / DIM;
            const int col = e - kk * DIM;
            const int g   = base + (kc + kk) * DIM + col;
            Bs[kk * BSTR + col] = make_float2(xre[g], xim[g]);
        }
        __syncthreads();

        if (active) {
            #pragma unroll 5
            for (int kk = 0; kk < KC; ++kk) {
                unsigned long long axx[5], ayn[5], bxy[4], byx[4];
                #pragma unroll
                for (int r = 0; r < 5; ++r) {
                    const float2 av = As[(i0 + r) * ASTR + kk];
                    axx[r] = pk2(av.x, av.x);
                    ayn[r] = pk2(-av.y, av.y);
                }
                #pragma unroll
                for (int c = 0; c < 4; ++c) {
                    const float2 bv = Bs[kk * BSTR + j0 + c];
                    bxy[c] = f2ull(bv);
                    byx[c] = pk2(bv.y, bv.x);
                }
                #pragma unroll
                for (int r = 0; r < 5; ++r)
                    #pragma unroll
                    for (int c = 0; c < 4; ++c) {
                        fma2(acc[r][c], axx[r], bxy[c]);
                        fma2(acc[r][c], ayn[r], byx[c]);
                    }
            }
        }
        __syncthreads();
    }

    if (active) {
        #pragma unroll
        for (int r = 0; r < 5; ++r) {
            // 4 consecutive float2 = 32B, 16B-aligned -> two float4 stores
            float4* p = reinterpret_cast<float4*>(
                &g_L[base + (i0 + r) * DIM + j0]);
            const float2 v0 = ull2f(acc[r][0]);
            const float2 v1 = ull2f(acc[r][1]);
            const float2 v2 = ull2f(acc[r][2]);
            const float2 v3 = ull2f(acc[r][3]);
            p[0] = make_float4(v0.x, v0.y, v1.x, v1.y);
            p[1] = make_float4(v2.x, v2.y, v3.x, v3.y);
        }
    }
}

// ---------------------------------------------------------------------------
// Kernel 3: GEMM2  Re(O_b) = Re(L_b @ U^H) = Lr@Ur^T + Li@Ui^T.
// Packed partial sums: acc = (s_even, s_odd); acc += (L.x,L.y)*(U.x,U.y);
// final ox = s_even + s_odd. Half the math of the complex version.
// Static smem 41.6 KB. Output: float32 real parts, float4-vectorized.
// ---------------------------------------------------------------------------
__global__ void __launch_bounds__(512)
gemm2_LUh(float* __restrict__ outf, int out_floats) {
    __shared__ float2 As[DIM * ASTR];   // L rows  [i][kk]
    __shared__ float2 Us[DIM * ASTR];   // U rows  [j][kk]

    const int b    = blockIdx.x;
    const int tid  = threadIdx.x;
    const int base = b * NN;

    const bool active = tid < 500;
    const int ti = tid / 25;
    const int tj = tid - ti * 25;
    const int i0 = ti * 5;
    const int j0 = tj * 4;

    unsigned long long acc[5][4];
    #pragma unroll
    for (int r = 0; r < 5; ++r)
        #pragma unroll
        for (int c = 0; c < 4; ++c) acc[r][c] = 0ull;

    for (int kc = 0; kc < DIM; kc += KC) {
        for (int e = tid; e < DIM * KC; e += 512) {
            const int row = e / KC;
            const int kk  = e - row * KC;
            As[row * ASTR + kk] = g_L[base + row * DIM + kc + kk];
            Us[row * ASTR + kk] = g_U[row * DIM + kc + kk];
        }
        __syncthreads();

        if (active) {
            #pragma unroll 5
            for (int kk = 0; kk < KC; ++kk) {
                unsigned long long ar[5], uc[4];
                #pragma unroll
                for (int r = 0; r < 5; ++r)
                    ar[r] = f2ull(As[(i0 + r) * ASTR + kk]);
                #pragma unroll
                for (int c = 0; c < 4; ++c)
                    uc[c] = f2ull(Us[(j0 + c) * ASTR + kk]);
                #pragma unroll
                for (int r = 0; r < 5; ++r)
                    #pragma unroll
                    for (int c = 0; c < 4; ++c)
                        fma2(acc[r][c], ar[r], uc[c]);
            }
        }
        __syncthreads();
    }

    if (active) {
        #pragma unroll
        for (int r = 0; r < 5; ++r) {
            const int idx = base + (i0 + r) * DIM + j0;   // 16B-aligned
            float v[4];
            #pragma unroll
            for (int c = 0; c < 4; ++c) {
                const float2 s = ull2f(acc[r][c]);
                v[c] = s.x + s.y;
            }
            if (idx + 3 < out_floats)
                *reinterpret_cast<float4*>(&outf[idx]) =
                    make_float4(v[0], v[1], v[2], v[3]);
        }
    }
}

// Diagnostic fallback: binding anomaly -> numeric mismatch, never a crash.
__global__ void diag_mark_kernel(float* out) { out[0] = 0.0f; }

extern "C" void kernel_launch(void* const* d_in, const int* in_sizes, int n_in,
                              void* d_out, int out_size) {
    // Unit detection (elements vs bytes) via the 100-element diag array.
    int smin = 0x7fffffff;
    for (int i = 0; i < n_in; ++i)
        if (in_sizes[i] < smin) smin = in_sizes[i];

    int unit = 0;
    if (smin == DIM)          unit = 1;
    else if (smin == DIM * 4) unit = 4;

    const float* xre = nullptr; const float* xim = nullptr;
    const float* theta = nullptr; const float* phi = nullptr;
    const float* diag = nullptr;
    int nbatch = 0, big = 0;
    bool ok = (unit != 0) && (n_in == 5);

    if (ok) {
        int norm[8];
        int diag_slot = -1;
        for (int i = 0; i < n_in; ++i) {
            norm[i] = in_sizes[i] / unit;
            if (norm[i] == DIM) diag_slot = i;
            if (norm[i] > big) big = norm[i];
        }
        if (diag_slot == 0 && norm[1] == KBS && norm[2] == KBS) {
            // alphabetical metadata order: diag, phi, theta, x_re, x_im
            diag  = (const float*)d_in[0];
            phi   = (const float*)d_in[1];
            theta = (const float*)d_in[2];
            xre   = (const float*)d_in[3];
            xim   = (const float*)d_in[4];
        } else {
            for (int i = 0; i < n_in; ++i) {
                const float* p = (const float*)d_in[i];
                if (norm[i] == KBS)      { if (!theta) theta = p; else phi = p; }
                else if (norm[i] == DIM) { diag = p; }
                else if (norm[i] == big) { if (!xre) xre = p; else xim = p; }
            }
        }
        nbatch = big / NN;
        ok = xre && xim && theta && phi && diag &&
             nbatch > 0 && nbatch <= MAXB && (big == nbatch * NN);
    }

    if (!ok) {
        diag_mark_kernel<<<1, 1>>>((float*)d_out);
        return;
    }

    // Confirmed output contract: float32 real parts, out_size = B*N*N floats.
    const int want = nbatch * NN;
    const int out_floats = (out_size < want) ? out_size : want;

    rot_prep<<<(KBS + 127) / 128, 128>>>(theta, phi, diag);
    build_U<<<DIM, 64>>>();
    gemm1_UX<<<nbatch, 512>>>(xre, xim);
    gemm2_LUh<<<nbatch, 512>>>((float*)d_out, out_floats);
}

// round 9
// speedup vs baseline: 2.7057x; 1.8661x over previous
#include <cuda_runtime.h>
#include <string.h>

#define DIM   100
#define KBS   4950
#define NN    (DIM * DIM)          // 10000
#define MAXB  2048
#define KC    25                   // K-chunk
#define ASTR  (KC + 1)             // 26, padded  (row-major [row][kk])
#define BSTR  (DIM + 1)            // 101, padded (chunk-major [kk][col])

// Sanctioned scratch (__device__ globals; no runtime allocation).
__device__ float2 g_U [NN];        // U[r][c]  row-major
__device__ float2 g_UT[NN];        // U^T: g_UT[l*DIM + j] = U[j][l]
__device__ float2 g_L [MAXB * NN];
__device__ float4 g_rot[KBS];      // {cos th, sin th, cos ph, sin ph}
__device__ float2 g_dph[DIM];      // {cos d, sin d}

// ---------------- packed f32x2 helpers (Blackwell f32x2 pipe) ----------------
__device__ __forceinline__ unsigned long long pk2(float lo, float hi) {
    unsigned long long r;
    asm("mov.b64 %0, {%1, %2};" : "=l"(r) : "f"(lo), "f"(hi));
    return r;
}
__device__ __forceinline__ unsigned long long f2ull(float2 v) {
    unsigned long long r; memcpy(&r, &v, 8); return r;
}
__device__ __forceinline__ float2 ull2f(unsigned long long v) {
    float2 f; memcpy(&f, &v, 8); return f;
}
__device__ __forceinline__ void fma2(unsigned long long& d,
                                     unsigned long long a,
                                     unsigned long long b) {
    asm("fma.rn.f32x2 %0, %1, %2, %0;" : "+l"(d) : "l"(a), "l"(b));
}

// ---------------------------------------------------------------------------
// Kernel 0: precompute rotation coefficients once.
// ---------------------------------------------------------------------------
__global__ void rot_prep(const float* __restrict__ theta,
                         const float* __restrict__ phi,
                         const float* __restrict__ diag) {
    const int i = blockIdx.x * blockDim.x + threadIdx.x;
    if (i < KBS) {
        float st, ct, sp, cp;
        sincosf(theta[i], &st, &ct);
        sincosf(phi[i],   &sp, &cp);
        g_rot[i] = make_float4(ct, st, cp, sp);
    }
    if (i < DIM) {
        float sd, cd;
        sincosf(diag[i], &sd, &cd);
        g_dph[i] = make_float2(cd, sd);
    }
}

// ---------------------------------------------------------------------------
// Kernel 1: build U = D * T_K ... T_1.  One CTA per column; serial layer scan.
// Software-prefetch next layer's coefficient to hide L2 latency behind the
// per-layer barrier. Writes both g_U (row-major) and g_UT (transposed).
// ---------------------------------------------------------------------------
__global__ void build_U() {
    __shared__ float2 col[DIM];
    const int c   = blockIdx.x;
    const int tid = threadIdx.x;          // blockDim = 64

    for (int r = tid; r < DIM; r += 64)
        col[r] = make_float2(r == c ? 1.0f : 0.0f, 0.0f);
    __syncthreads();

    // prefetch layer 0 coefficient
    float4 rc_next = make_float4(1.f, 0.f, 1.f, 0.f);
    if (tid < 50) rc_next = g_rot[tid];

    int off = 0;
    for (int layer = 0; layer < DIM; ++layer) {
        const int start = layer & 1;
        const int np    = (DIM - start) >> 1;
        const float4 rc = rc_next;

        // prefetch next layer's coefficient (hides L2 latency behind barrier)
        const int noff = off + np;
        if (layer + 1 < DIM) {
            const int nstart = (layer + 1) & 1;
            const int nnp    = (DIM - nstart) >> 1;
            if (tid < nnp) rc_next = g_rot[noff + tid];
        }

        if (tid < np) {
            const int m = start + 2 * tid;
            const float2 rm = col[m];
            const float2 rn = col[m + 1];
            const float er = rc.z * rm.x - rc.w * rm.y;   // e^{i ph} * rm
            const float ei = rc.z * rm.y + rc.w * rm.x;
            col[m]     = make_float2(rc.x * er - rc.y * rn.x,
                                     rc.x * ei - rc.y * rn.y);
            col[m + 1] = make_float2(rc.y * er + rc.x * rn.x,
                                     rc.y * ei + rc.x * rn.y);
        }
        off = noff;
        __syncthreads();
    }

    for (int r = tid; r < DIM; r += 64) {
        const float2 d = g_dph[r];
        const float2 v = col[r];
        const float2 u = make_float2(d.x * v.x - d.y * v.y,
                                     d.x * v.y + d.y * v.x);
        g_U [r * DIM + c] = u;   // U[r][c]
        g_UT[c * DIM + r] = u;   // U^T[c][r] = U[r][c]  (coalesced in r)
    }
}

// ---------------------------------------------------------------------------
// Kernel 2: GEMM1  L_b = U @ X_b  (full complex).
// Thread (ti,tj): rows i0..i0+4 (broadcast A loads), columns {tj + 25c}.
// B loads Bs[kk][25c+tj]: consecutive tj -> consecutive float2 -> NO bank
// conflicts (round-8 ncu showed L1=93% from ~8-way conflicts on old mapping).
// ---------------------------------------------------------------------------
__global__ void __launch_bounds__(512)
gemm1_UX(const float* __restrict__ xre, const float* __restrict__ xim) {
    __shared__ float2 As[DIM * ASTR];   // U rows   [row][kk]
    __shared__ float2 Bs[KC * BSTR];    // X chunk  [kk][col]

    const int b    = blockIdx.x;
    const int tid  = threadIdx.x;
    const int base = b * NN;

    const bool active = tid < 500;
    const int ti = tid / 25;
    const int tj = tid - ti * 25;
    const int i0 = ti * 5;

    unsigned long long acc[5][4];
    #pragma unroll
    for (int r = 0; r < 5; ++r)
        #pragma unroll
        for (int c = 0; c < 4; ++c) acc[r][c] = 0ull;

    for (int kc = 0; kc < DIM; kc += KC) {
        for (int e = tid; e < DIM * KC; e += 512) {
            const int row = e / KC;
            const int kk  = e - row * KC;
            As[row * ASTR + kk] = g_U[row * DIM + kc + kk];
        }
        for (int e = tid; e < KC * DIM; e += 512) {
            const int kk  = e / DIM;
            const int col = e - kk * DIM;
            const int g   = base + (kc + kk) * DIM + col;
            Bs[kk * BSTR + col] = make_float2(xre[g], xim[g]);
        }
        __syncthreads();

        if (active) {
            #pragma unroll 5
            for (int kk = 0; kk < KC; ++kk) {
                unsigned long long axx[5], ayn[5], bxy[4], byx[4];
                #pragma unroll
                for (int r = 0; r < 5; ++r) {
                    const float2 av = As[(i0 + r) * ASTR + kk];   // broadcast
                    axx[r] = pk2(av.x, av.x);
                    ayn[r] = pk2(-av.y, av.y);
                }
                #pragma unroll
                for (int c = 0; c < 4; ++c) {
                    const float2 bv = Bs[kk * BSTR + 25 * c + tj]; // conflict-free
                    bxy[c] = f2ull(bv);
                    byx[c] = pk2(bv.y, bv.x);
                }
                #pragma unroll
                for (int r = 0; r < 5; ++r)
                    #pragma unroll
                    for (int c = 0; c < 4; ++c) {
                        fma2(acc[r][c], axx[r], bxy[c]);
                        fma2(acc[r][c], ayn[r], byx[c]);
                    }
            }
        }
        __syncthreads();
    }

    if (active) {
        #pragma unroll
        for (int r = 0; r < 5; ++r)
            #pragma unroll
            for (int c = 0; c < 4; ++c)
                g_L[base + (i0 + r) * DIM + 25 * c + tj] = ull2f(acc[r][c]);
    }
}

// ---------------------------------------------------------------------------
// Kernel 3: GEMM2  Re(O_b) = Lr@Ur^T + Li@Ui^T, packed even/odd partials.
// U staged TRANSPOSED from g_UT -> UsT[kk][j]; u loads UsT[kk][25c+tj] are
// conflict-free. 2 CTAs/SM for latency hiding (41KB smem, <=64 regs).
// ---------------------------------------------------------------------------
__global__ void __launch_bounds__(512, 2)
gemm2_LUh(float* __restrict__ outf, int out_floats) {
    __shared__ float2 As [DIM * ASTR];  // L rows   [i][kk]
    __shared__ float2 UsT[KC * BSTR];   // U^T chunk [kk][j]

    const int b    = blockIdx.x;
    const int tid  = threadIdx.x;
    const int base = b * NN;

    const bool active = tid < 500;
    const int ti = tid / 25;
    const int tj = tid - ti * 25;
    const int i0 = ti * 5;

    unsigned long long acc[5][4];
    #pragma unroll
    for (int r = 0; r < 5; ++r)
        #pragma unroll
        for (int c = 0; c < 4; ++c) acc[r][c] = 0ull;

    for (int kc = 0; kc < DIM; kc += KC) {
        for (int e = tid; e < DIM * KC; e += 512) {
            const int row = e / KC;
            const int kk  = e - row * KC;
            As[row * ASTR + kk] = g_L[base + row * DIM + kc + kk];
        }
        for (int e = tid; e < KC * DIM; e += 512) {
            const int kk = e / DIM;
            const int j  = e - kk * DIM;
            UsT[kk * BSTR + j] = g_UT[(kc + kk) * DIM + j];   // coalesced
        }
        __syncthreads();

        if (active) {
            #pragma unroll 5
            for (int kk = 0; kk < KC; ++kk) {
                unsigned long long ar[5], uc[4];
                #pragma unroll
                for (int r = 0; r < 5; ++r)
                    ar[r] = f2ull(As[(i0 + r) * ASTR + kk]);      // broadcast
                #pragma unroll
                for (int c = 0; c < 4; ++c)
                    uc[c] = f2ull(UsT[kk * BSTR + 25 * c + tj]);  // conflict-free
                #pragma unroll
                for (int r = 0; r < 5; ++r)
                    #pragma unroll
                    for (int c = 0; c < 4; ++c)
                        fma2(acc[r][c], ar[r], uc[c]);
            }
        }
        __syncthreads();
    }

    if (active) {
        #pragma unroll
        for (int r = 0; r < 5; ++r)
            #pragma unroll
            for (int c = 0; c < 4; ++c) {
                const int idx = base + (i0 + r) * DIM + 25 * c + tj;
                const float2 s = ull2f(acc[r][c]);
                if (idx < out_floats)
                    outf[idx] = s.x + s.y;      // Re = even + odd partial
            }
    }
}

// Diagnostic fallback: binding anomaly -> numeric mismatch, never a crash.
__global__ void diag_mark_kernel(float* out) { out[0] = 0.0f; }

extern "C" void kernel_launch(void* const* d_in, const int* in_sizes, int n_in,
                              void* d_out, int out_size) {
    // Unit detection (elements vs bytes) via the 100-element diag array.
    int smin = 0x7fffffff;
    for (int i = 0; i < n_in; ++i)
        if (in_sizes[i] < smin) smin = in_sizes[i];

    int unit = 0;
    if (smin == DIM)          unit = 1;
    else if (smin == DIM * 4) unit = 4;

    const float* xre = nullptr; const float* xim = nullptr;
    const float* theta = nullptr; const float* phi = nullptr;
    const float* diag = nullptr;
    int nbatch = 0, big = 0;
    bool ok = (unit != 0) && (n_in == 5);

    if (ok) {
        int norm[8];
        int diag_slot = -1;
        for (int i = 0; i < n_in; ++i) {
            norm[i] = in_sizes[i] / unit;
            if (norm[i] == DIM) diag_slot = i;
            if (norm[i] > big) big = norm[i];
        }
        if (diag_slot == 0 && norm[1] == KBS && norm[2] == KBS) {
            // alphabetical metadata order: diag, phi, theta, x_re, x_im
            diag  = (const float*)d_in[0];
            phi   = (const float*)d_in[1];
            theta = (const float*)d_in[2];
            xre   = (const float*)d_in[3];
            xim   = (const float*)d_in[4];
        } else {
            for (int i = 0; i < n_in; ++i) {
                const float* p = (const float*)d_in[i];
                if (norm[i] == KBS)      { if (!theta) theta = p; else phi = p; }
                else if (norm[i] == DIM) { diag = p; }
                else if (norm[i] == big) { if (!xre) xre = p; else xim = p; }
            }
        }
        nbatch = big / NN;
        ok = xre && xim && theta && phi && diag &&
             nbatch > 0 && nbatch <= MAXB && (big == nbatch * NN);
    }

    if (!ok) {
        diag_mark_kernel<<<1, 1>>>((float*)d_out);
        return;
    }

    // Confirmed output contract: float32 real parts, out_size = B*N*N floats.
    const int want = nbatch * NN;
    const int out_floats = (out_size < want) ? out_size : want;

    rot_prep<<<(KBS + 127) / 128, 128>>>(theta, phi, diag);
    build_U<<<DIM, 64>>>();
    gemm1_UX<<<nbatch, 512>>>(xre, xim);
    gemm2_LUh<<<nbatch, 512>>>((float*)d_out, out_floats);
}

// round 10
// speedup vs baseline: 2.7066x; 1.0004x over previous
#include <cuda_runtime.h>
#include <string.h>

#define DIM   100
#define KBS   4950
#define NN    (DIM * DIM)          // 10000
#define MAXB  2048
#define KC    25                   // K-chunk
#define ASTR  (KC + 1)             // 26, padded  (row-major [row][kk])
#define BSTR  (DIM + 1)            // 101, padded (chunk-major [kk][col])

// Sanctioned scratch (__device__ globals; no runtime allocation).
__device__ float2 g_U [NN];        // U[r][c]  row-major
__device__ float2 g_UT[NN];        // U^T: g_UT[l*DIM + j] = U[j][l]
__device__ float2 g_L [MAXB * NN];
__device__ float4 g_rot[KBS];      // {cos th, sin th, cos ph, sin ph}
__device__ float2 g_dph[DIM];      // {cos d, sin d}

// ---------------- packed f32x2 helpers (Blackwell f32x2 pipe) ----------------
__device__ __forceinline__ unsigned long long pk2(float lo, float hi) {
    unsigned long long r;
    asm("mov.b64 %0, {%1, %2};" : "=l"(r) : "f"(lo), "f"(hi));
    return r;
}
__device__ __forceinline__ unsigned long long f2ull(float2 v) {
    unsigned long long r; memcpy(&r, &v, 8); return r;
}
__device__ __forceinline__ float2 ull2f(unsigned long long v) {
    float2 f; memcpy(&f, &v, 8); return f;
}
__device__ __forceinline__ void fma2(unsigned long long& d,
                                     unsigned long long a,
                                     unsigned long long b) {
    asm("fma.rn.f32x2 %0, %1, %2, %0;" : "+l"(d) : "l"(a), "l"(b));
}

// ---------------------------------------------------------------------------
// Kernel 0: precompute rotation coefficients once.
// ---------------------------------------------------------------------------
__global__ void rot_prep(const float* __restrict__ theta,
                         const float* __restrict__ phi,
                         const float* __restrict__ diag) {
    const int i = blockIdx.x * blockDim.x + threadIdx.x;
    if (i < KBS) {
        float st, ct, sp, cp;
        sincosf(theta[i], &st, &ct);
        sincosf(phi[i],   &sp, &cp);
        g_rot[i] = make_float4(ct, st, cp, sp);
    }
    if (i < DIM) {
        float sd, cd;
        sincosf(diag[i], &sd, &cd);
        g_dph[i] = make_float2(cd, sd);
    }
}

// ---------------------------------------------------------------------------
// Kernel 1: build U = D * T_K ... T_1.  One CTA per column; serial layer scan.
// Software-prefetch next layer's coefficient to hide L2 latency behind the
// per-layer barrier. Writes both g_U (row-major) and g_UT (transposed).
// ---------------------------------------------------------------------------
__global__ void build_U() {
    __shared__ float2 col[DIM];
    const int c   = blockIdx.x;
    const int tid = threadIdx.x;          // blockDim = 64

    for (int r = tid; r < DIM; r += 64)
        col[r] = make_float2(r == c ? 1.0f : 0.0f, 0.0f);
    __syncthreads();

    // prefetch layer 0 coefficient
    float4 rc_next = make_float4(1.f, 0.f, 1.f, 0.f);
    if (tid < 50) rc_next = g_rot[tid];

    int off = 0;
    for (int layer = 0; layer < DIM; ++layer) {
        const int start = layer & 1;
        const int np    = (DIM - start) >> 1;
        const float4 rc = rc_next;

        // prefetch next layer's coefficient (hides L2 latency behind barrier)
        const int noff = off + np;
        if (layer + 1 < DIM) {
            const int nstart = (layer + 1) & 1;
            const int nnp    = (DIM - nstart) >> 1;
            if (tid < nnp) rc_next = g_rot[noff + tid];
        }

        if (tid < np) {
            const int m = start + 2 * tid;
            const float2 rm = col[m];
            const float2 rn = col[m + 1];
            const float er = rc.z * rm.x - rc.w * rm.y;   // e^{i ph} * rm
            const float ei = rc.z * rm.y + rc.w * rm.x;
            col[m]     = make_float2(rc.x * er - rc.y * rn.x,
                                     rc.x * ei - rc.y * rn.y);
            col[m + 1] = make_float2(rc.y * er + rc.x * rn.x,
                                     rc.y * ei + rc.x * rn.y);
        }
        off = noff;
        __syncthreads();
    }

    for (int r = tid; r < DIM; r += 64) {
        const float2 d = g_dph[r];
        const float2 v = col[r];
        const float2 u = make_float2(d.x * v.x - d.y * v.y,
                                     d.x * v.y + d.y * v.x);
        g_U [r * DIM + c] = u;   // U[r][c]
        g_UT[c * DIM + r] = u;   // U^T[c][r] = U[r][c]  (coalesced in r)
    }
}

// ---------------------------------------------------------------------------
// Kernel 2: GEMM1  L_b = U @ X_b  (full complex).
// Thread (ti,tj): rows i0..i0+4 (broadcast A loads), columns {tj + 25c}.
// B loads Bs[kk][25c+tj]: consecutive tj -> consecutive float2 -> NO bank
// conflicts (round-8 ncu showed L1=93% from ~8-way conflicts on old mapping).
// ---------------------------------------------------------------------------
__global__ void __launch_bounds__(512)
gemm1_UX(const float* __restrict__ xre, const float* __restrict__ xim) {
    __shared__ float2 As[DIM * ASTR];   // U rows   [row][kk]
    __shared__ float2 Bs[KC * BSTR];    // X chunk  [kk][col]

    const int b    = blockIdx.x;
    const int tid  = threadIdx.x;
    const int base = b * NN;

    const bool active = tid < 500;
    const int ti = tid / 25;
    const int tj = tid - ti * 25;
    const int i0 = ti * 5;

    unsigned long long acc[5][4];
    #pragma unroll
    for (int r = 0; r < 5; ++r)
        #pragma unroll
        for (int c = 0; c < 4; ++c) acc[r][c] = 0ull;

    for (int kc = 0; kc < DIM; kc += KC) {
        for (int e = tid; e < DIM * KC; e += 512) {
            const int row = e / KC;
            const int kk  = e - row * KC;
            As[row * ASTR + kk] = g_U[row * DIM + kc + kk];
        }
        for (int e = tid; e < KC * DIM; e += 512) {
            const int kk  = e / DIM;
            const int col = e - kk * DIM;
            const int g   = base + (kc + kk) * DIM + col;
            Bs[kk * BSTR + col] = make_float2(xre[g], xim[g]);
        }
        __syncthreads();

        if (active) {
            #pragma unroll 5
            for (int kk = 0; kk < KC; ++kk) {
                unsigned long long axx[5], ayn[5], bxy[4], byx[4];
                #pragma unroll
                for (int r = 0; r < 5; ++r) {
                    const float2 av = As[(i0 + r) * ASTR + kk];   // broadcast
                    axx[r] = pk2(av.x, av.x);
                    ayn[r] = pk2(-av.y, av.y);
                }
                #pragma unroll
                for (int c = 0; c < 4; ++c) {
                    const float2 bv = Bs[kk * BSTR + 25 * c + tj]; // conflict-free
                    bxy[c] = f2ull(bv);
                    byx[c] = pk2(bv.y, bv.x);
                }
                #pragma unroll
                for (int r = 0; r < 5; ++r)
                    #pragma unroll
                    for (int c = 0; c < 4; ++c) {
                        fma2(acc[r][c], axx[r], bxy[c]);
                        fma2(acc[r][c], ayn[r], byx[c]);
                    }
            }
        }
        __syncthreads();
    }

    if (active) {
        #pragma unroll
        for (int r = 0; r < 5; ++r)
            #pragma unroll
            for (int c = 0; c < 4; ++c)
                g_L[base + (i0 + r) * DIM + 25 * c + tj] = ull2f(acc[r][c]);
    }
}

// ---------------------------------------------------------------------------
// Kernel 3: GEMM2  Re(O_b) = Lr@Ur^T + Li@Ui^T, packed even/odd partials.
// U staged TRANSPOSED from g_UT -> UsT[kk][j]; u loads UsT[kk][25c+tj] are
// conflict-free. 2 CTAs/SM for latency hiding (41KB smem, <=64 regs).
// ---------------------------------------------------------------------------
__global__ void __launch_bounds__(512, 2)
gemm2_LUh(float* __restrict__ outf, int out_floats) {
    __shared__ float2 As [DIM * ASTR];  // L rows   [i][kk]
    __shared__ float2 UsT[KC * BSTR];   // U^T chunk [kk][j]

    const int b    = blockIdx.x;
    const int tid  = threadIdx.x;
    const int base = b * NN;

    const bool active = tid < 500;
    const int ti = tid / 25;
    const int tj = tid - ti * 25;
    const int i0 = ti * 5;

    unsigned long long acc[5][4];
    #pragma unroll
    for (int r = 0; r < 5; ++r)
        #pragma unroll
        for (int c = 0; c < 4; ++c) acc[r][c] = 0ull;

    for (int kc = 0; kc < DIM; kc += KC) {
        for (int e = tid; e < DIM * KC; e += 512) {
            const int row = e / KC;
            const int kk  = e - row * KC;
            As[row * ASTR + kk] = g_L[base + row * DIM + kc + kk];
        }
        for (int e = tid; e < KC * DIM; e += 512) {
            const int kk = e / DIM;
            const int j  = e - kk * DIM;
            UsT[kk * BSTR + j] = g_UT[(kc + kk) * DIM + j];   // coalesced
        }
        __syncthreads();

        if (active) {
            #pragma unroll 5
            for (int kk = 0; kk < KC; ++kk) {
                unsigned long long ar[5], uc[4];
                #pragma unroll
                for (int r = 0; r < 5; ++r)
                    ar[r] = f2ull(As[(i0 + r) * ASTR + kk]);      // broadcast
                #pragma unroll
                for (int c = 0; c < 4; ++c)
                    uc[c] = f2ull(UsT[kk * BSTR + 25 * c + tj]);  // conflict-free
                #pragma unroll
                for (int r = 0; r < 5; ++r)
                    #pragma unroll
                    for (int c = 0; c < 4; ++c)
                        fma2(acc[r][c], ar[r], uc[c]);
            }
        }
        __syncthreads();
    }

    if (active) {
        #pragma unroll
        for (int r = 0; r < 5; ++r)
            #pragma unroll
            for (int c = 0; c < 4; ++c) {
                const int idx = base + (i0 + r) * DIM + 25 * c + tj;
                const float2 s = ull2f(acc[r][c]);
                if (idx < out_floats)
                    outf[idx] = s.x + s.y;      // Re = even + odd partial
            }
    }
}

// Diagnostic fallback: binding anomaly -> numeric mismatch, never a crash.
__global__ void diag_mark_kernel(float* out) { out[0] = 0.0f; }

extern "C" void kernel_launch(void* const* d_in, const int* in_sizes, int n_in,
                              void* d_out, int out_size) {
    // Unit detection (elements vs bytes) via the 100-element diag array.
    int smin = 0x7fffffff;
    for (int i = 0; i < n_in; ++i)
        if (in_sizes[i] < smin) smin = in_sizes[i];

    int unit = 0;
    if (smin == DIM)          unit = 1;
    else if (smin == DIM * 4) unit = 4;

    const float* xre = nullptr; const float* xim = nullptr;
    const float* theta = nullptr; const float* phi = nullptr;
    const float* diag = nullptr;
    int nbatch = 0, big = 0;
    bool ok = (unit != 0) && (n_in == 5);

    if (ok) {
        int norm[8];
        int diag_slot = -1;
        for (int i = 0; i < n_in; ++i) {
            norm[i] = in_sizes[i] / unit;
            if (norm[i] == DIM) diag_slot = i;
            if (norm[i] > big) big = norm[i];
        }
        if (diag_slot == 0 && norm[1] == KBS && norm[2] == KBS) {
            // alphabetical metadata order: diag, phi, theta, x_re, x_im
            diag  = (const float*)d_in[0];
            phi   = (const float*)d_in[1];
            theta = (const float*)d_in[2];
            xre   = (const float*)d_in[3];
            xim   = (const float*)d_in[4];
        } else {
            for (int i = 0; i < n_in; ++i) {
                const float* p = (const float*)d_in[i];
                if (norm[i] == KBS)      { if (!theta) theta = p; else phi = p; }
                else if (norm[i] == DIM) { diag = p; }
                else if (norm[i] == big) { if (!xre) xre = p; else xim = p; }
            }
        }
        nbatch = big / NN;
        ok = xre && xim && theta && phi && diag &&
             nbatch > 0 && nbatch <= MAXB && (big == nbatch * NN);
    }

    if (!ok) {
        diag_mark_kernel<<<1, 1>>>((float*)d_out);
        return;
    }

    // Confirmed output contract: float32 real parts, out_size = B*N*N floats.
    const int want = nbatch * NN;
    const int out_floats = (out_size < want) ? out_size : want;

    rot_prep<<<(KBS + 127) / 128, 128>>>(theta, phi, diag);
    build_U<<<DIM, 64>>>();
    gemm1_UX<<<nbatch, 512>>>(xre, xim);
    gemm2_LUh<<<nbatch, 512>>>((float*)d_out, out_floats);
}